// round 1
// baseline (speedup 1.0000x reference)
#include <cuda_runtime.h>
#include <math.h>

// Problem constants
#define BB 4
#define SS 2048
#define DD 1024
#define HH 16
#define HDIM 64
#define FFD 4096
#define MM (BB * SS)   // 8192

// ---------------- scratch (device globals; no allocation allowed) ----------
__device__ float g_q[(size_t)MM * DD];
__device__ float g_k[(size_t)MM * DD];
__device__ float g_v[(size_t)MM * DD];
__device__ float g_ctx[(size_t)MM * DD];
__device__ float g_attn[(size_t)MM * DD];
__device__ float g_ff[(size_t)MM * FFD];

// ---------------- GEMM: C[M,N] = A[M,K] @ B[K,N] + bias[N] (opt relu) ------
// 128x128 block tile, BK=8, 256 threads, 8x8 per-thread tile (2x2 of 4x4),
// float4 global loads with register prefetch.
#define BM 128
#define BN 128
#define BK 8

__global__ void __launch_bounds__(256, 2)
gemm_bias_kernel(const float* __restrict__ A, const float* __restrict__ B,
                 const float* __restrict__ bias, float* __restrict__ C,
                 int M, int N, int K, int relu)
{
    __shared__ float As[BK][BM];
    __shared__ float Bs[BK][BN];

    const int tid  = threadIdx.x;
    const int brow = blockIdx.y * BM;
    const int bcol = blockIdx.x * BN;

    // compute-tile coords: rows {row0..+3, row0+64..+67}, cols likewise
    const int row0 = (tid / 16) * 4;
    const int col0 = (tid % 16) * 4;

    // loader coords
    const int arow  = tid >> 1;          // 0..127
    const int acol4 = (tid & 1) * 4;     // 0 or 4
    const int bkrow = tid >> 5;          // 0..7
    const int bcol4 = (tid & 31) * 4;    // 0..124

    const float* Ag = A + (size_t)(brow + arow) * K + acol4;
    const float* Bg = B + (size_t)bkrow * N + bcol + bcol4;

    float acc[8][8];
    #pragma unroll
    for (int i = 0; i < 8; i++)
        #pragma unroll
        for (int j = 0; j < 8; j++) acc[i][j] = 0.f;

    float4 av = *(const float4*)Ag;
    float4 bv = *(const float4*)Bg;

    for (int k0 = 0; k0 < K; k0 += BK) {
        As[acol4 + 0][arow] = av.x;
        As[acol4 + 1][arow] = av.y;
        As[acol4 + 2][arow] = av.z;
        As[acol4 + 3][arow] = av.w;
        *(float4*)&Bs[bkrow][bcol4] = bv;
        __syncthreads();

        if (k0 + BK < K) {  // prefetch next tile into registers
            av = *(const float4*)(Ag + k0 + BK);
            bv = *(const float4*)(Bg + (size_t)(k0 + BK) * N);
        }

        #pragma unroll
        for (int kk = 0; kk < BK; kk++) {
            float a[8], b[8];
            float4 a0 = *(const float4*)&As[kk][row0];
            float4 a1 = *(const float4*)&As[kk][row0 + 64];
            float4 b0 = *(const float4*)&Bs[kk][col0];
            float4 b1 = *(const float4*)&Bs[kk][col0 + 64];
            a[0]=a0.x; a[1]=a0.y; a[2]=a0.z; a[3]=a0.w;
            a[4]=a1.x; a[5]=a1.y; a[6]=a1.z; a[7]=a1.w;
            b[0]=b0.x; b[1]=b0.y; b[2]=b0.z; b[3]=b0.w;
            b[4]=b1.x; b[5]=b1.y; b[6]=b1.z; b[7]=b1.w;
            #pragma unroll
            for (int i = 0; i < 8; i++)
                #pragma unroll
                for (int j = 0; j < 8; j++)
                    acc[i][j] += a[i] * b[j];
        }
        __syncthreads();
    }

    // epilogue: +bias, optional relu, vectorized stores
    #pragma unroll
    for (int i = 0; i < 8; i++) {
        int r = brow + ((i < 4) ? (row0 + i) : (row0 + 64 + (i - 4)));
        #pragma unroll
        for (int jg = 0; jg < 2; jg++) {
            int c = bcol + col0 + jg * 64;
            float4 bb = *(const float4*)(bias + c);
            float4 v;
            v.x = acc[i][jg * 4 + 0] + bb.x;
            v.y = acc[i][jg * 4 + 1] + bb.y;
            v.z = acc[i][jg * 4 + 2] + bb.z;
            v.w = acc[i][jg * 4 + 3] + bb.w;
            if (relu) {
                v.x = fmaxf(v.x, 0.f); v.y = fmaxf(v.y, 0.f);
                v.z = fmaxf(v.z, 0.f); v.w = fmaxf(v.w, 0.f);
            }
            *(float4*)(C + (size_t)r * N + c) = v;
        }
    }
}

// ---------------- attention: flash-style, fp32 -----------------------------
// grid: (S/QT, H, B), 128 threads; thread owns one query row.
// Mask is a suffix (kpos >= length) -> just truncate the key loop.
#define QT 128
#define KT 64

__global__ void __launch_bounds__(128)
attn_kernel(const float* __restrict__ Q, const float* __restrict__ K,
            const float* __restrict__ V, const int* __restrict__ lengths,
            float* __restrict__ O)
{
    __shared__ float Ksh[KT][HDIM];
    __shared__ float Vsh[KT][HDIM];

    const int b   = blockIdx.z;
    const int h   = blockIdx.y;
    const int q0  = blockIdx.x * QT;
    const int tid = threadIdx.x;
    const int len = lengths[b];

    // load this thread's query row into registers
    float q[HDIM];
    const float* qrow = Q + ((size_t)(b * SS) + q0 + tid) * DD + h * HDIM;
    #pragma unroll
    for (int d = 0; d < HDIM; d += 4) {
        float4 t = *(const float4*)(qrow + d);
        q[d] = t.x; q[d + 1] = t.y; q[d + 2] = t.z; q[d + 3] = t.w;
    }

    float acc[HDIM];
    #pragma unroll
    for (int d = 0; d < HDIM; d++) acc[d] = 0.f;
    float m = -1e30f, l = 0.f;
    const float scale = 0.125f;  // 1/sqrt(64)

    const int ntiles = (len + KT - 1) / KT;
    for (int t = 0; t < ntiles; t++) {
        const int kbase = t * KT;
        __syncthreads();
        // cooperative K/V tile load (KT x HDIM each)
        for (int i = tid; i < KT * (HDIM / 4); i += 128) {
            int kr = i / (HDIM / 4);
            int dc = (i % (HDIM / 4)) * 4;
            size_t goff = ((size_t)(b * SS) + kbase + kr) * DD + h * HDIM + dc;
            *(float4*)&Ksh[kr][dc] = *(const float4*)(K + goff);
            *(float4*)&Vsh[kr][dc] = *(const float4*)(V + goff);
        }
        __syncthreads();

        const int kmax = min(KT, len - kbase);
        for (int k = 0; k < kmax; k++) {
            float dot = 0.f;
            #pragma unroll
            for (int d = 0; d < HDIM; d++) dot += q[d] * Ksh[k][d];
            float sv = dot * scale;
            if (sv > m) {
                float alpha = __expf(m - sv);
                m = sv;
                l *= alpha;
                #pragma unroll
                for (int d = 0; d < HDIM; d++) acc[d] *= alpha;
            }
            float p = __expf(sv - m);
            l += p;
            #pragma unroll
            for (int d = 0; d < HDIM; d++) acc[d] += p * Vsh[k][d];
        }
    }

    const float inv = 1.f / l;
    float* orow = O + ((size_t)(b * SS) + q0 + tid) * DD + h * HDIM;
    #pragma unroll
    for (int d = 0; d < HDIM; d += 4) {
        float4 v;
        v.x = acc[d] * inv;     v.y = acc[d + 1] * inv;
        v.z = acc[d + 2] * inv; v.w = acc[d + 3] * inv;
        *(float4*)(orow + d) = v;
    }
}

// ---------------- launch ----------------------------------------------------
static float* sym_addr(const void* sym) {
    void* p = nullptr;
    cudaGetSymbolAddress(&p, sym);
    return (float*)p;
}

extern "C" void kernel_launch(void* const* d_in, const int* in_sizes, int n_in,
                              void* d_out, int out_size)
{
    const float* x   = (const float*)d_in[0];
    const int*   len = (const int*)  d_in[1];
    const float* qW  = (const float*)d_in[2];
    const float* qb  = (const float*)d_in[3];
    const float* kW  = (const float*)d_in[4];
    const float* kb  = (const float*)d_in[5];
    const float* vW  = (const float*)d_in[6];
    const float* vb  = (const float*)d_in[7];
    const float* oW  = (const float*)d_in[8];
    const float* ob  = (const float*)d_in[9];
    const float* w1  = (const float*)d_in[10];
    const float* b1  = (const float*)d_in[11];
    const float* w2  = (const float*)d_in[12];
    const float* b2  = (const float*)d_in[13];
    float* out = (float*)d_out;

    // symbol addresses resolved once on the (pre-capture) correctness call
    static float* pq   = sym_addr(g_q);
    static float* pk   = sym_addr(g_k);
    static float* pv   = sym_addr(g_v);
    static float* pctx = sym_addr(g_ctx);
    static float* patt = sym_addr(g_attn);
    static float* pff  = sym_addr(g_ff);

    dim3 thr(256);
    dim3 gD(DD / BN, MM / BM);    // N=1024 GEMMs
    dim3 gF(FFD / BN, MM / BM);   // N=4096 GEMM

    gemm_bias_kernel<<<gD, thr>>>(x, qW, qb, pq, MM, DD, DD, 0);
    gemm_bias_kernel<<<gD, thr>>>(x, kW, kb, pk, MM, DD, DD, 0);
    gemm_bias_kernel<<<gD, thr>>>(x, vW, vb, pv, MM, DD, DD, 0);

    dim3 ga(SS / QT, HH, BB);
    attn_kernel<<<ga, 128>>>(pq, pk, pv, len, pctx);

    gemm_bias_kernel<<<gD, thr>>>(pctx, oW, ob, patt, MM, DD, DD, 0);
    gemm_bias_kernel<<<gF, thr>>>(patt, w1, b1, pff, MM, FFD, DD, 1);
    gemm_bias_kernel<<<gD, thr>>>(pff, w2, b2, out, MM, DD, FFD, 0);
}

// round 3
// speedup vs baseline: 1.1600x; 1.1600x over previous
#include <cuda_runtime.h>
#include <math.h>
#include <stdint.h>

// ---------------- problem constants ----------------------------------------
#define BB 4
#define SS 2048
#define DD 1024
#define HH 16
#define HDIM 64
#define FFD 4096
#define MM (BB * SS)   // 8192

// ---------------- scratch (device globals; no allocation allowed) ----------
__device__ float g_q  [(size_t)MM * DD];
__device__ float g_k  [(size_t)MM * DD];
__device__ float g_v  [(size_t)MM * DD];
__device__ float g_ctx[(size_t)MM * DD];
__device__ float g_att[(size_t)MM * DD];
__device__ float g_ff [(size_t)MM * FFD];
__device__ float g_wt [12u * 1024u * 1024u];  // transposed weights [N][K]

// ---------------- helpers ----------------------------------------------------
__device__ __forceinline__ uint32_t smem_u32(const void* p) {
    uint32_t a;
    asm("{ .reg .u64 t; cvta.to.shared.u64 t, %1; cvt.u32.u64 %0, t; }" : "=r"(a) : "l"(p));
    return a;
}
__device__ __forceinline__ uint32_t tf32_rna(float x) {
    uint32_t r;
    asm("cvt.rna.tf32.f32 %0, %1;" : "=r"(r) : "f"(x));
    return r;
}
__device__ __forceinline__ void cp_async16(uint32_t dst, const void* src) {
    asm volatile("cp.async.cg.shared.global [%0], [%1], 16;" :: "r"(dst), "l"(src));
}
#define CP_COMMIT() asm volatile("cp.async.commit_group;" ::: "memory")
#define CP_WAIT(n)  asm volatile("cp.async.wait_group %0;" :: "n"(n) : "memory")

__device__ __forceinline__ void mma_tf32(float* c, const uint32_t* a, const uint32_t* b) {
    asm volatile(
        "mma.sync.aligned.m16n8k8.row.col.f32.tf32.tf32.f32 "
        "{%0,%1,%2,%3}, {%4,%5,%6,%7}, {%8,%9}, {%0,%1,%2,%3};"
        : "+f"(c[0]), "+f"(c[1]), "+f"(c[2]), "+f"(c[3])
        : "r"(a[0]), "r"(a[1]), "r"(a[2]), "r"(a[3]), "r"(b[0]), "r"(b[1]));
}

// ---------------- tf32 mma.sync GEMM ----------------------------------------
// C[M,N] = A[M,K] @ Wt^T + bias  (Wt: [N][K] row-major)
// CTA 128x256, BK=16, 8 warps (2m x 4n), warp tile 64x64, 4-stage cp.async.
// PASSES: 1 = plain tf32; 2 = A-side exact (a_hi+a_lo)*b_hi; 3 = tf32x3.
#define GBM 128
#define GBN 256
#define GBK 16
#define LDP 20                       // padded row stride (floats): conflict-free
#define A_F (GBM * LDP)              // 2560 floats
#define B_F (GBN * LDP)              // 5120 floats
#define STAGE_F (A_F + B_F)          // 7680 floats
#define NSTG 4
#define GEMM_SMEM (NSTG * STAGE_F * 4)   // 122880 bytes

template<int PASSES>
__global__ void __launch_bounds__(256, 1)
gemm_tc(const float* __restrict__ A, const float* __restrict__ Bt,
        const float* __restrict__ bias, float* __restrict__ C,
        int N, int K, int relu)
{
    extern __shared__ float sm[];
    const uint32_t sb = smem_u32(sm);

    const int tid = threadIdx.x, wid = tid >> 5, lane = tid & 31;
    const int wm = wid & 1;     // 0..1  (64 rows each)
    const int wn = wid >> 1;    // 0..3  (64 cols each)
    const int lr = lane >> 2;   // 0..7
    const int lc = lane & 3;    // 0..3

    const int brow = blockIdx.y * GBM;
    const int bcol = blockIdx.x * GBN;
    const int ktiles = K / GBK;

    // load-index precompute (each thread: 2 A-float4s, 4 B-float4s per stage)
    const int am[2]  = { (tid) >> 2, (tid + 256) >> 2 };
    const int ak4    = (tid & 3) * 4;
    const int bn[4]  = { tid >> 2, (tid + 256) >> 2, (tid + 512) >> 2, (tid + 768) >> 2 };

    float acc[4][8][4];
    #pragma unroll
    for (int i = 0; i < 4; i++)
        #pragma unroll
        for (int j = 0; j < 8; j++)
            #pragma unroll
            for (int r = 0; r < 4; r++) acc[i][j][r] = 0.f;

    // ---- prefetch helper (as macro-ish lambda) ----
    auto prefetch = [&](int kt, int s) {
        uint32_t sA = sb + (uint32_t)(s * STAGE_F) * 4u;
        uint32_t sB = sA + A_F * 4u;
        #pragma unroll
        for (int i = 0; i < 2; i++) {
            int m = am[i];
            cp_async16(sA + (m * LDP + ak4) * 4,
                       A + (size_t)(brow + m) * K + kt * GBK + ak4);
        }
        #pragma unroll
        for (int i = 0; i < 4; i++) {
            int n = bn[i];
            cp_async16(sB + (n * LDP + ak4) * 4,
                       Bt + (size_t)(bcol + n) * K + kt * GBK + ak4);
        }
        CP_COMMIT();
    };

    int issued = 0;
    #pragma unroll
    for (int s = 0; s < NSTG - 1; s++) {
        if (issued < ktiles) { prefetch(issued, issued & (NSTG - 1)); issued++; }
    }

    for (int kt = 0; kt < ktiles; kt++) {
        // ensure stage kt arrived
        int pending = issued - kt - 1;
        if (pending >= 2)      CP_WAIT(2);
        else if (pending == 1) CP_WAIT(1);
        else                   CP_WAIT(0);
        __syncthreads();

        if (issued < ktiles) { prefetch(issued, issued & (NSTG - 1)); issued++; }

        const float* As = sm + (kt & (NSTG - 1)) * STAGE_F;
        const float* Bs = As + A_F;

        #pragma unroll
        for (int k8 = 0; k8 < GBK; k8 += 8) {
            uint32_t ah[4][4], al[4][4];
            #pragma unroll
            for (int mt = 0; mt < 4; mt++) {
                const int r0 = wm * 64 + mt * 16;
                float f0 = As[(r0 + lr)     * LDP + k8 + lc];
                float f1 = As[(r0 + lr + 8) * LDP + k8 + lc];
                float f2 = As[(r0 + lr)     * LDP + k8 + lc + 4];
                float f3 = As[(r0 + lr + 8) * LDP + k8 + lc + 4];
                ah[mt][0] = tf32_rna(f0); ah[mt][1] = tf32_rna(f1);
                ah[mt][2] = tf32_rna(f2); ah[mt][3] = tf32_rna(f3);
                if (PASSES >= 2) {
                    al[mt][0] = tf32_rna(f0 - __uint_as_float(ah[mt][0]));
                    al[mt][1] = tf32_rna(f1 - __uint_as_float(ah[mt][1]));
                    al[mt][2] = tf32_rna(f2 - __uint_as_float(ah[mt][2]));
                    al[mt][3] = tf32_rna(f3 - __uint_as_float(ah[mt][3]));
                }
            }
            uint32_t bh[8][2], bl[8][2];
            #pragma unroll
            for (int nt = 0; nt < 8; nt++) {
                const int n0 = wn * 64 + nt * 8;
                float f0 = Bs[(n0 + lr) * LDP + k8 + lc];
                float f1 = Bs[(n0 + lr) * LDP + k8 + lc + 4];
                bh[nt][0] = tf32_rna(f0); bh[nt][1] = tf32_rna(f1);
                if (PASSES >= 3) {
                    bl[nt][0] = tf32_rna(f0 - __uint_as_float(bh[nt][0]));
                    bl[nt][1] = tf32_rna(f1 - __uint_as_float(bh[nt][1]));
                }
            }
            #pragma unroll
            for (int mt = 0; mt < 4; mt++)
                #pragma unroll
                for (int nt = 0; nt < 8; nt++)
                    mma_tf32(acc[mt][nt], ah[mt], bh[nt]);
            if (PASSES >= 2) {
                #pragma unroll
                for (int mt = 0; mt < 4; mt++)
                    #pragma unroll
                    for (int nt = 0; nt < 8; nt++)
                        mma_tf32(acc[mt][nt], al[mt], bh[nt]);
            }
            if (PASSES >= 3) {
                #pragma unroll
                for (int mt = 0; mt < 4; mt++)
                    #pragma unroll
                    for (int nt = 0; nt < 8; nt++)
                        mma_tf32(acc[mt][nt], ah[mt], bl[nt]);
            }
        }
    }

    // ---- epilogue ----
    #pragma unroll
    for (int mt = 0; mt < 4; mt++) {
        const int gr = brow + wm * 64 + mt * 16 + lr;
        #pragma unroll
        for (int nt = 0; nt < 8; nt++) {
            const int gc = bcol + wn * 64 + nt * 8 + lc * 2;
            float2 bb = *(const float2*)(bias + gc);
            float2 v0, v1;
            v0.x = acc[mt][nt][0] + bb.x;  v0.y = acc[mt][nt][1] + bb.y;
            v1.x = acc[mt][nt][2] + bb.x;  v1.y = acc[mt][nt][3] + bb.y;
            if (relu) {
                v0.x = fmaxf(v0.x, 0.f); v0.y = fmaxf(v0.y, 0.f);
                v1.x = fmaxf(v1.x, 0.f); v1.y = fmaxf(v1.y, 0.f);
            }
            *(float2*)(C + (size_t)gr * N + gc)       = v0;
            *(float2*)(C + (size_t)(gr + 8) * N + gc) = v1;
        }
    }
}

// ---------------- weight transpose ------------------------------------------
// in[R][C] -> out[C][R]
__global__ void transpose_k(const float* __restrict__ in, float* __restrict__ out,
                            int R, int C)
{
    __shared__ float t[32][33];
    int c0 = blockIdx.x * 32, r0 = blockIdx.y * 32;
    for (int i = threadIdx.y; i < 32; i += 8)
        t[i][threadIdx.x] = in[(size_t)(r0 + i) * C + c0 + threadIdx.x];
    __syncthreads();
    for (int i = threadIdx.y; i < 32; i += 8)
        out[(size_t)(c0 + i) * R + r0 + threadIdx.x] = t[threadIdx.x][i];
}

// ---------------- attention: flash-style fp32, 16-key score batching --------
#define QT 128
#define KT 64
#define CH 16

__global__ void __launch_bounds__(128)
attn_kernel(const float* __restrict__ Q, const float* __restrict__ K,
            const float* __restrict__ V, const int* __restrict__ lengths,
            float* __restrict__ O)
{
    __shared__ float Ksh[KT][HDIM];
    __shared__ float Vsh[KT][HDIM];

    const int b   = blockIdx.z;
    const int h   = blockIdx.y;
    const int q0  = blockIdx.x * QT;
    const int tid = threadIdx.x;
    const int len = lengths[b];

    float q[HDIM];
    const float* qrow = Q + ((size_t)(b * SS) + q0 + tid) * DD + h * HDIM;
    #pragma unroll
    for (int d = 0; d < HDIM; d += 4) {
        float4 t = *(const float4*)(qrow + d);
        q[d] = t.x; q[d + 1] = t.y; q[d + 2] = t.z; q[d + 3] = t.w;
    }

    float acc[HDIM];
    #pragma unroll
    for (int d = 0; d < HDIM; d++) acc[d] = 0.f;
    float m = -1e30f, l = 0.f;
    const float scale = 0.125f;

    const int ntiles = (len + KT - 1) / KT;
    for (int t = 0; t < ntiles; t++) {
        const int kbase = t * KT;
        __syncthreads();
        for (int i = tid; i < KT * (HDIM / 4); i += 128) {
            int kr = i / (HDIM / 4);
            int dc = (i % (HDIM / 4)) * 4;
            size_t goff = ((size_t)(b * SS) + kbase + kr) * DD + h * HDIM + dc;
            *(float4*)&Ksh[kr][dc] = *(const float4*)(K + goff);
            *(float4*)&Vsh[kr][dc] = *(const float4*)(V + goff);
        }
        __syncthreads();

        const int kmax = min(KT, len - kbase);
        for (int base = 0; base < kmax; base += CH) {
            float s[CH];
            float tmax = -1e30f;
            #pragma unroll
            for (int k = 0; k < CH; k++) {
                const int kk = base + k;
                float dot = 0.f;
                #pragma unroll
                for (int d = 0; d < HDIM; d++) dot += q[d] * Ksh[kk][d];
                s[k] = (kk < kmax) ? dot * scale : -1e30f;
                tmax = fmaxf(tmax, s[k]);
            }
            if (tmax > m) {
                float alpha = __expf(m - tmax);
                m = tmax;
                l *= alpha;
                #pragma unroll
                for (int d = 0; d < HDIM; d++) acc[d] *= alpha;
            }
            float psum = 0.f;
            #pragma unroll
            for (int k = 0; k < CH; k++) {
                float p = __expf(s[k] - m);
                psum += p;
                #pragma unroll
                for (int d = 0; d < HDIM; d++) acc[d] += p * Vsh[base + k][d];
            }
            l += psum;
        }
    }

    const float inv = 1.f / l;
    float* orow = O + ((size_t)(b * SS) + q0 + tid) * DD + h * HDIM;
    #pragma unroll
    for (int d = 0; d < HDIM; d += 4) {
        float4 v;
        v.x = acc[d] * inv;     v.y = acc[d + 1] * inv;
        v.z = acc[d + 2] * inv; v.w = acc[d + 3] * inv;
        *(float4*)(orow + d) = v;
    }
}

// ---------------- host side --------------------------------------------------
static float* sym_addr(const void* sym) {
    void* p = nullptr;
    cudaGetSymbolAddress(&p, sym);
    return (float*)p;
}

extern "C" void kernel_launch(void* const* d_in, const int* in_sizes, int n_in,
                              void* d_out, int out_size)
{
    const float* x   = (const float*)d_in[0];
    const int*   len = (const int*)  d_in[1];
    const float* qW  = (const float*)d_in[2];
    const float* qb  = (const float*)d_in[3];
    const float* kW  = (const float*)d_in[4];
    const float* kb  = (const float*)d_in[5];
    const float* vW  = (const float*)d_in[6];
    const float* vb  = (const float*)d_in[7];
    const float* oW  = (const float*)d_in[8];
    const float* ob  = (const float*)d_in[9];
    const float* w1  = (const float*)d_in[10];
    const float* b1  = (const float*)d_in[11];
    const float* w2  = (const float*)d_in[12];
    const float* b2  = (const float*)d_in[13];
    float* out = (float*)d_out;

    static float* pq   = sym_addr(g_q);
    static float* pk   = sym_addr(g_k);
    static float* pv   = sym_addr(g_v);
    static float* pctx = sym_addr(g_ctx);
    static float* patt = sym_addr(g_att);
    static float* pff  = sym_addr(g_ff);
    static float* pwt  = sym_addr(g_wt);

    static bool inited = false;
    if (!inited) {
        cudaFuncSetAttribute(gemm_tc<2>, cudaFuncAttributeMaxDynamicSharedMemorySize, GEMM_SMEM);
        cudaFuncSetAttribute(gemm_tc<3>, cudaFuncAttributeMaxDynamicSharedMemorySize, GEMM_SMEM);
        inited = true;
    }

    float* wt_q  = pwt;
    float* wt_k  = pwt + 1u * 1024u * 1024u;
    float* wt_v  = pwt + 2u * 1024u * 1024u;
    float* wt_o  = pwt + 3u * 1024u * 1024u;
    float* wt_w1 = pwt + 4u * 1024u * 1024u;
    float* wt_w2 = pwt + 8u * 1024u * 1024u;

    dim3 tb(32, 8);
    transpose_k<<<dim3(32, 32), tb>>>(qW, wt_q, DD, DD);
    transpose_k<<<dim3(32, 32), tb>>>(kW, wt_k, DD, DD);
    transpose_k<<<dim3(32, 32), tb>>>(vW, wt_v, DD, DD);
    transpose_k<<<dim3(32, 32), tb>>>(oW, wt_o, DD, DD);
    transpose_k<<<dim3(FFD / 32, 32), tb>>>(w1, wt_w1, DD, FFD);    // [D,FF] -> [FF,D]
    transpose_k<<<dim3(32, FFD / 32), tb>>>(w2, wt_w2, FFD, DD);    // [FF,D] -> [D,FF]

    dim3 thr(256);
    dim3 gD(DD / GBN, MM / GBM);    // (4, 64)
    dim3 gF(FFD / GBN, MM / GBM);   // (16, 64)

    // Q/K: tf32x3 (precise — softmax amplifies logit error); others tf32x2
    gemm_tc<3><<<gD, thr, GEMM_SMEM>>>(x, wt_q, qb, pq, DD, DD, 0);
    gemm_tc<3><<<gD, thr, GEMM_SMEM>>>(x, wt_k, kb, pk, DD, DD, 0);
    gemm_tc<2><<<gD, thr, GEMM_SMEM>>>(x, wt_v, vb, pv, DD, DD, 0);

    dim3 ga(SS / QT, HH, BB);
    attn_kernel<<<ga, 128>>>(pq, pk, pv, len, pctx);

    gemm_tc<2><<<gD, thr, GEMM_SMEM>>>(pctx, wt_o, ob, patt, DD, DD, 0);
    gemm_tc<2><<<gF, thr, GEMM_SMEM>>>(patt, wt_w1, b1, pff, FFD, DD, 1);
    gemm_tc<2><<<gD, thr, GEMM_SMEM>>>(pff, wt_w2, b2, out, DD, FFD, 0);
}

// round 4
// speedup vs baseline: 1.4586x; 1.2574x over previous
#include <cuda_runtime.h>
#include <cuda_bf16.h>
#include <math.h>
#include <stdint.h>

// ---------------- problem constants ----------------------------------------
#define BB 4
#define SS 2048
#define DD 1024
#define HH 16
#define HDIM 64
#define FFD 4096
#define MM (BB * SS)   // 8192

// ---------------- scratch (device globals; no allocation allowed) ----------
__device__ float g_q[(size_t)MM * DD];
__device__ float g_k[(size_t)MM * DD];
__device__ float g_v[(size_t)MM * DD];
__device__ __nv_bfloat16 g_xh[(size_t)MM * DD],  g_xl[(size_t)MM * DD];
__device__ __nv_bfloat16 g_ch[(size_t)MM * DD],  g_cl[(size_t)MM * DD];   // ctx
__device__ __nv_bfloat16 g_th[(size_t)MM * DD],  g_tl[(size_t)MM * DD];   // attn-out
__device__ __nv_bfloat16 g_fh[(size_t)MM * FFD], g_fl[(size_t)MM * FFD];  // ffn hidden
__device__ __nv_bfloat16 g_wh[12u * 1024u * 1024u];
__device__ __nv_bfloat16 g_wl[12u * 1024u * 1024u];

// ---------------- helpers ----------------------------------------------------
__device__ __forceinline__ uint32_t smem_u32(const void* p) {
    uint32_t a;
    asm("{ .reg .u64 t; cvta.to.shared.u64 t, %1; cvt.u32.u64 %0, t; }" : "=r"(a) : "l"(p));
    return a;
}
__device__ __forceinline__ void cp_async16(uint32_t dst, const void* src) {
    asm volatile("cp.async.cg.shared.global [%0], [%1], 16;" :: "r"(dst), "l"(src));
}
#define CP_COMMIT() asm volatile("cp.async.commit_group;" ::: "memory")
#define CP_WAIT(n)  asm volatile("cp.async.wait_group %0;" :: "n"(n) : "memory")

__device__ __forceinline__ void mma_bf16(float* c, const uint32_t* a, uint32_t b0, uint32_t b1) {
    asm volatile(
        "mma.sync.aligned.m16n8k16.row.col.f32.bf16.bf16.f32 "
        "{%0,%1,%2,%3}, {%4,%5,%6,%7}, {%8,%9}, {%0,%1,%2,%3};"
        : "+f"(c[0]), "+f"(c[1]), "+f"(c[2]), "+f"(c[3])
        : "r"(a[0]), "r"(a[1]), "r"(a[2]), "r"(a[3]), "r"(b0), "r"(b1));
}

__device__ __forceinline__ void store_split2(__nv_bfloat16* __restrict__ H,
                                             __nv_bfloat16* __restrict__ L,
                                             size_t off, float x, float y) {
    __nv_bfloat16 hx = __float2bfloat16(x), hy = __float2bfloat16(y);
    __nv_bfloat16 lx = __float2bfloat16(x - __bfloat162float(hx));
    __nv_bfloat16 ly = __float2bfloat16(y - __bfloat162float(hy));
    __nv_bfloat162 h2; h2.x = hx; h2.y = hy;
    __nv_bfloat162 l2; l2.x = lx; l2.y = ly;
    *(__nv_bfloat162*)(H + off) = h2;
    *(__nv_bfloat162*)(L + off) = l2;
}

// ---------------- bf16x3 mma.sync GEMM ---------------------------------------
// C[M,N] = (Ah+Al)[M,K] @ (Bh+Bl)^T + bias   (B stored [N][K] K-major)
// CTA 128x256, BK=32 bf16, 8 warps (2m x 4n), warp tile 64x64, 3-stage cp.async.
// 3 MMA terms: ah*bh + al*bh + ah*bl  (error ~2^-18).
#define GBM 128
#define GBN 256
#define GBK 32
#define SROW 80                         // bytes per smem row (32 bf16 + pad)
#define SA_H 0
#define SA_L (128 * SROW)               // 10240
#define SB_H (2 * 128 * SROW)           // 20480
#define SB_L (SB_H + 256 * SROW)        // 40960
#define STG_B (SB_L + 256 * SROW)       // 61440
#define NSTG 3
#define GEMM_SMEM (NSTG * STG_B)        // 184320

template<int OUTBF>
__global__ void __launch_bounds__(256, 1)
gemm_bf16x3(const __nv_bfloat16* __restrict__ Ah, const __nv_bfloat16* __restrict__ Al,
            const __nv_bfloat16* __restrict__ Bh, const __nv_bfloat16* __restrict__ Bl,
            const float* __restrict__ bias,
            float* __restrict__ Cf,
            __nv_bfloat16* __restrict__ Ch, __nv_bfloat16* __restrict__ Cl,
            int N, int K, int relu)
{
    extern __shared__ char sm[];
    const uint32_t sb = smem_u32(sm);
    const int tid = threadIdx.x, wid = tid >> 5, lane = tid & 31;
    const int wm = wid & 1, wn = wid >> 1;
    const int g = lane >> 2, tg = lane & 3;
    const int brow = blockIdx.y * GBM, bcol = blockIdx.x * GBN;
    const int ktiles = K / GBK;

    float acc[4][8][4];
    #pragma unroll
    for (int i = 0; i < 4; i++)
        #pragma unroll
        for (int j = 0; j < 8; j++)
            #pragma unroll
            for (int r = 0; r < 4; r++) acc[i][j][r] = 0.f;

    auto prefetch = [&](int kt) {
        uint32_t st = sb + (uint32_t)((kt % NSTG) * STG_B);
        const int koff = kt * GBK;
        #pragma unroll
        for (int i = 0; i < 2; i++) {
            int c = tid + i * 256, row = c >> 2, o = (c & 3) * 8;
            cp_async16(st + SA_H + row * SROW + o * 2,
                       Ah + (size_t)(brow + row) * K + koff + o);
            cp_async16(st + SA_L + row * SROW + o * 2,
                       Al + (size_t)(brow + row) * K + koff + o);
        }
        #pragma unroll
        for (int i = 0; i < 4; i++) {
            int c = tid + i * 256, row = c >> 2, o = (c & 3) * 8;
            cp_async16(st + SB_H + row * SROW + o * 2,
                       Bh + (size_t)(bcol + row) * K + koff + o);
            cp_async16(st + SB_L + row * SROW + o * 2,
                       Bl + (size_t)(bcol + row) * K + koff + o);
        }
        CP_COMMIT();
    };

    int issued = 0;
    for (; issued < NSTG - 1 && issued < ktiles; issued++) prefetch(issued);

    for (int kt = 0; kt < ktiles; kt++) {
        int pending = issued - kt - 1;
        if (pending >= 2)      CP_WAIT(2);
        else if (pending == 1) CP_WAIT(1);
        else                   CP_WAIT(0);
        __syncthreads();
        if (issued < ktiles) { prefetch(issued); issued++; }

        const char* stg = sm + (kt % NSTG) * STG_B;
        #pragma unroll
        for (int kk = 0; kk < GBK; kk += 16) {
            const int cby = (kk + tg * 2) * 2;   // byte offset of this thread's k pair
            uint32_t fah[4][4], fal[4][4];
            #pragma unroll
            for (int mt = 0; mt < 4; mt++) {
                const int r = wm * 64 + mt * 16 + g;
                const char* ph = stg + SA_H;
                const char* pl = stg + SA_L;
                fah[mt][0] = *(const uint32_t*)(ph + r * SROW + cby);
                fah[mt][1] = *(const uint32_t*)(ph + (r + 8) * SROW + cby);
                fah[mt][2] = *(const uint32_t*)(ph + r * SROW + cby + 16);
                fah[mt][3] = *(const uint32_t*)(ph + (r + 8) * SROW + cby + 16);
                fal[mt][0] = *(const uint32_t*)(pl + r * SROW + cby);
                fal[mt][1] = *(const uint32_t*)(pl + (r + 8) * SROW + cby);
                fal[mt][2] = *(const uint32_t*)(pl + r * SROW + cby + 16);
                fal[mt][3] = *(const uint32_t*)(pl + (r + 8) * SROW + cby + 16);
            }
            #pragma unroll
            for (int nt = 0; nt < 8; nt++) {
                const int n = wn * 64 + nt * 8 + g;
                uint32_t bh0 = *(const uint32_t*)(stg + SB_H + n * SROW + cby);
                uint32_t bh1 = *(const uint32_t*)(stg + SB_H + n * SROW + cby + 16);
                uint32_t bl0 = *(const uint32_t*)(stg + SB_L + n * SROW + cby);
                uint32_t bl1 = *(const uint32_t*)(stg + SB_L + n * SROW + cby + 16);
                #pragma unroll
                for (int mt = 0; mt < 4; mt++) mma_bf16(acc[mt][nt], fah[mt], bh0, bh1);
                #pragma unroll
                for (int mt = 0; mt < 4; mt++) mma_bf16(acc[mt][nt], fal[mt], bh0, bh1);
                #pragma unroll
                for (int mt = 0; mt < 4; mt++) mma_bf16(acc[mt][nt], fah[mt], bl0, bl1);
            }
        }
    }

    // ---- epilogue ----
    #pragma unroll
    for (int mt = 0; mt < 4; mt++) {
        const int gr = brow + wm * 64 + mt * 16 + g;
        #pragma unroll
        for (int nt = 0; nt < 8; nt++) {
            const int gc = bcol + wn * 64 + nt * 8 + tg * 2;
            float2 bb = *(const float2*)(bias + gc);
            float v0x = acc[mt][nt][0] + bb.x, v0y = acc[mt][nt][1] + bb.y;
            float v1x = acc[mt][nt][2] + bb.x, v1y = acc[mt][nt][3] + bb.y;
            if (relu) {
                v0x = fmaxf(v0x, 0.f); v0y = fmaxf(v0y, 0.f);
                v1x = fmaxf(v1x, 0.f); v1y = fmaxf(v1y, 0.f);
            }
            if (OUTBF == 0) {
                float2 a = {v0x, v0y}, b = {v1x, v1y};
                *(float2*)(Cf + (size_t)gr * N + gc)       = a;
                *(float2*)(Cf + (size_t)(gr + 8) * N + gc) = b;
            } else {
                store_split2(Ch, Cl, (size_t)gr * N + gc, v0x, v0y);
                store_split2(Ch, Cl, (size_t)(gr + 8) * N + gc, v1x, v1y);
            }
        }
    }
}

// ---------------- preprocessing ----------------------------------------------
__global__ void split_f32(const float* __restrict__ in,
                          __nv_bfloat16* __restrict__ H, __nv_bfloat16* __restrict__ L, int n2)
{
    int i = blockIdx.x * blockDim.x + threadIdx.x;
    if (i < n2) {
        float2 v = ((const float2*)in)[i];
        store_split2(H, L, (size_t)i * 2, v.x, v.y);
    }
}

// in[R][C] fp32 -> out[C][R] bf16 hi/lo
__global__ void transpose_split(const float* __restrict__ in,
                                __nv_bfloat16* __restrict__ OH, __nv_bfloat16* __restrict__ OL,
                                int R, int C)
{
    __shared__ float t[32][33];
    int c0 = blockIdx.x * 32, r0 = blockIdx.y * 32;
    for (int i = threadIdx.y; i < 32; i += 8)
        t[i][threadIdx.x] = in[(size_t)(r0 + i) * C + c0 + threadIdx.x];
    __syncthreads();
    for (int i = threadIdx.y; i < 32; i += 8) {
        float v = t[threadIdx.x][i];
        __nv_bfloat16 h = __float2bfloat16(v);
        __nv_bfloat16 l = __float2bfloat16(v - __bfloat162float(h));
        OH[(size_t)(c0 + i) * R + r0 + threadIdx.x] = h;
        OL[(size_t)(c0 + i) * R + r0 + threadIdx.x] = l;
    }
}

// ---------------- attention: flash-style fp32, writes bf16 hi/lo ctx ---------
#define QT 128
#define KT 64
#define CH 16

__global__ void __launch_bounds__(128)
attn_kernel(const float* __restrict__ Q, const float* __restrict__ K,
            const float* __restrict__ V, const int* __restrict__ lengths,
            __nv_bfloat16* __restrict__ CtxH, __nv_bfloat16* __restrict__ CtxL)
{
    __shared__ float Ksh[KT][HDIM];
    __shared__ float Vsh[KT][HDIM];

    const int b    = blockIdx.z;
    const int head = blockIdx.y;
    const int q0   = blockIdx.x * QT;
    const int tid  = threadIdx.x;
    const int len  = lengths[b];

    float q[HDIM];
    const float* qrow = Q + ((size_t)(b * SS) + q0 + tid) * DD + head * HDIM;
    #pragma unroll
    for (int d = 0; d < HDIM; d += 4) {
        float4 t = *(const float4*)(qrow + d);
        q[d] = t.x; q[d + 1] = t.y; q[d + 2] = t.z; q[d + 3] = t.w;
    }

    float acc[HDIM];
    #pragma unroll
    for (int d = 0; d < HDIM; d++) acc[d] = 0.f;
    float m = -1e30f, l = 0.f;
    const float scale = 0.125f;

    const int ntiles = (len + KT - 1) / KT;
    for (int t = 0; t < ntiles; t++) {
        const int kbase = t * KT;
        __syncthreads();
        for (int i = tid; i < KT * (HDIM / 4); i += 128) {
            int kr = i / (HDIM / 4);
            int dc = (i % (HDIM / 4)) * 4;
            size_t goff = ((size_t)(b * SS) + kbase + kr) * DD + head * HDIM + dc;
            *(float4*)&Ksh[kr][dc] = *(const float4*)(K + goff);
            *(float4*)&Vsh[kr][dc] = *(const float4*)(V + goff);
        }
        __syncthreads();

        const int kmax = min(KT, len - kbase);
        for (int base = 0; base < kmax; base += CH) {
            float s[CH];
            float tmax = -1e30f;
            #pragma unroll
            for (int k = 0; k < CH; k++) {
                const int kk = base + k;
                float dot = 0.f;
                #pragma unroll
                for (int d = 0; d < HDIM; d++) dot += q[d] * Ksh[kk][d];
                s[k] = (kk < kmax) ? dot * scale : -1e30f;
                tmax = fmaxf(tmax, s[k]);
            }
            if (tmax > m) {
                float alpha = __expf(m - tmax);
                m = tmax;
                l *= alpha;
                #pragma unroll
                for (int d = 0; d < HDIM; d++) acc[d] *= alpha;
            }
            float psum = 0.f;
            #pragma unroll
            for (int k = 0; k < CH; k++) {
                float p = __expf(s[k] - m);
                psum += p;
                #pragma unroll
                for (int d = 0; d < HDIM; d++) acc[d] += p * Vsh[base + k][d];
            }
            l += psum;
        }
    }

    const float inv = 1.f / l;
    const size_t obase = ((size_t)(b * SS) + q0 + tid) * DD + head * HDIM;
    #pragma unroll
    for (int d = 0; d < HDIM; d += 2)
        store_split2(CtxH, CtxL, obase + d, acc[d] * inv, acc[d + 1] * inv);
}

// ---------------- host side --------------------------------------------------
template<typename T>
static T* sym_addr(const void* sym) {
    void* p = nullptr;
    cudaGetSymbolAddress(&p, sym);
    return (T*)p;
}

extern "C" void kernel_launch(void* const* d_in, const int* in_sizes, int n_in,
                              void* d_out, int out_size)
{
    const float* x   = (const float*)d_in[0];
    const int*   len = (const int*)  d_in[1];
    const float* qW  = (const float*)d_in[2];
    const float* qb  = (const float*)d_in[3];
    const float* kW  = (const float*)d_in[4];
    const float* kb  = (const float*)d_in[5];
    const float* vW  = (const float*)d_in[6];
    const float* vb  = (const float*)d_in[7];
    const float* oW  = (const float*)d_in[8];
    const float* ob  = (const float*)d_in[9];
    const float* w1  = (const float*)d_in[10];
    const float* b1  = (const float*)d_in[11];
    const float* w2  = (const float*)d_in[12];
    const float* b2  = (const float*)d_in[13];
    float* out = (float*)d_out;

    typedef __nv_bfloat16 bf;
    static float* pq  = sym_addr<float>(g_q);
    static float* pk  = sym_addr<float>(g_k);
    static float* pv  = sym_addr<float>(g_v);
    static bf* pxh = sym_addr<bf>(g_xh);  static bf* pxl = sym_addr<bf>(g_xl);
    static bf* pch = sym_addr<bf>(g_ch);  static bf* pcl = sym_addr<bf>(g_cl);
    static bf* pth = sym_addr<bf>(g_th);  static bf* ptl = sym_addr<bf>(g_tl);
    static bf* pfh = sym_addr<bf>(g_fh);  static bf* pfl = sym_addr<bf>(g_fl);
    static bf* pwh = sym_addr<bf>(g_wh);  static bf* pwl = sym_addr<bf>(g_wl);

    static bool inited = false;
    if (!inited) {
        cudaFuncSetAttribute(gemm_bf16x3<0>, cudaFuncAttributeMaxDynamicSharedMemorySize, GEMM_SMEM);
        cudaFuncSetAttribute(gemm_bf16x3<1>, cudaFuncAttributeMaxDynamicSharedMemorySize, GEMM_SMEM);
        inited = true;
    }

    const uint32_t M1 = 1024u * 1024u;
    bf *wq_h = pwh,          *wq_l = pwl;
    bf *wk_h = pwh + 1 * M1, *wk_l = pwl + 1 * M1;
    bf *wv_h = pwh + 2 * M1, *wv_l = pwl + 2 * M1;
    bf *wo_h = pwh + 3 * M1, *wo_l = pwl + 3 * M1;
    bf *w1_h = pwh + 4 * M1, *w1_l = pwl + 4 * M1;
    bf *w2_h = pwh + 8 * M1, *w2_l = pwl + 8 * M1;

    // preprocess: split x; transpose+split all weights to [N][K] bf16 hi/lo
    split_f32<<<(MM * DD / 2 + 255) / 256, 256>>>(x, pxh, pxl, MM * DD / 2);
    dim3 tb(32, 8);
    transpose_split<<<dim3(32, 32), tb>>>(qW, wq_h, wq_l, DD, DD);
    transpose_split<<<dim3(32, 32), tb>>>(kW, wk_h, wk_l, DD, DD);
    transpose_split<<<dim3(32, 32), tb>>>(vW, wv_h, wv_l, DD, DD);
    transpose_split<<<dim3(32, 32), tb>>>(oW, wo_h, wo_l, DD, DD);
    transpose_split<<<dim3(FFD / 32, 32), tb>>>(w1, w1_h, w1_l, DD, FFD);  // -> [FF][D]
    transpose_split<<<dim3(32, FFD / 32), tb>>>(w2, w2_h, w2_l, FFD, DD);  // -> [D][FF]

    dim3 thr(256);
    dim3 gD(DD / GBN, MM / GBM);    // (4, 64)
    dim3 gF(FFD / GBN, MM / GBM);   // (16, 64)

    gemm_bf16x3<0><<<gD, thr, GEMM_SMEM>>>(pxh, pxl, wq_h, wq_l, qb, pq, nullptr, nullptr, DD, DD, 0);
    gemm_bf16x3<0><<<gD, thr, GEMM_SMEM>>>(pxh, pxl, wk_h, wk_l, kb, pk, nullptr, nullptr, DD, DD, 0);
    gemm_bf16x3<0><<<gD, thr, GEMM_SMEM>>>(pxh, pxl, wv_h, wv_l, vb, pv, nullptr, nullptr, DD, DD, 0);

    dim3 ga(SS / QT, HH, BB);
    attn_kernel<<<ga, 128>>>(pq, pk, pv, len, pch, pcl);

    gemm_bf16x3<1><<<gD, thr, GEMM_SMEM>>>(pch, pcl, wo_h, wo_l, ob, nullptr, pth, ptl, DD, DD, 0);
    gemm_bf16x3<1><<<gF, thr, GEMM_SMEM>>>(pth, ptl, w1_h, w1_l, b1, nullptr, pfh, pfl, FFD, DD, 1);
    gemm_bf16x3<0><<<gD, thr, GEMM_SMEM>>>(pfh, pfl, w2_h, w2_l, b2, out, nullptr, nullptr, DD, FFD, 0);
}

// round 5
// speedup vs baseline: 1.4600x; 1.0009x over previous
#include <cuda_runtime.h>
#include <cuda_bf16.h>
#include <math.h>
#include <stdint.h>

// ---------------- problem constants ----------------------------------------
#define BB 4
#define SS 2048
#define DD 1024
#define HH 16
#define HDIM 64
#define FFD 4096
#define MM (BB * SS)   // 8192

// ---------------- scratch (device globals; no allocation allowed) ----------
__device__ float g_q[(size_t)MM * DD];
__device__ float g_k[(size_t)MM * DD];
__device__ float g_v[(size_t)MM * DD];
__device__ __nv_bfloat16 g_xh[(size_t)MM * DD],  g_xl[(size_t)MM * DD];
__device__ __nv_bfloat16 g_ch[(size_t)MM * DD],  g_cl[(size_t)MM * DD];   // ctx
__device__ __nv_bfloat16 g_th[(size_t)MM * DD],  g_tl[(size_t)MM * DD];   // attn-out
__device__ __nv_bfloat16 g_fh[(size_t)MM * FFD], g_fl[(size_t)MM * FFD];  // ffn hidden
__device__ __nv_bfloat16 g_wh[12u * 1024u * 1024u];
__device__ __nv_bfloat16 g_wl[12u * 1024u * 1024u];

// ---------------- helpers ----------------------------------------------------
__device__ __forceinline__ uint32_t smem_u32(const void* p) {
    uint32_t a;
    asm("{ .reg .u64 t; cvta.to.shared.u64 t, %1; cvt.u32.u64 %0, t; }" : "=r"(a) : "l"(p));
    return a;
}
__device__ __forceinline__ void cp_async16(uint32_t dst, const void* src) {
    asm volatile("cp.async.cg.shared.global [%0], [%1], 16;" :: "r"(dst), "l"(src));
}
#define CP_COMMIT() asm volatile("cp.async.commit_group;" ::: "memory")
#define CP_WAIT(n)  asm volatile("cp.async.wait_group %0;" :: "n"(n) : "memory")

__device__ __forceinline__ void mma_bf16(float* c, const uint32_t* a, uint32_t b0, uint32_t b1) {
    asm volatile(
        "mma.sync.aligned.m16n8k16.row.col.f32.bf16.bf16.f32 "
        "{%0,%1,%2,%3}, {%4,%5,%6,%7}, {%8,%9}, {%0,%1,%2,%3};"
        : "+f"(c[0]), "+f"(c[1]), "+f"(c[2]), "+f"(c[3])
        : "r"(a[0]), "r"(a[1]), "r"(a[2]), "r"(a[3]), "r"(b0), "r"(b1));
}

__device__ __forceinline__ void store_split2(__nv_bfloat16* __restrict__ H,
                                             __nv_bfloat16* __restrict__ L,
                                             size_t off, float x, float y) {
    __nv_bfloat16 hx = __float2bfloat16(x), hy = __float2bfloat16(y);
    __nv_bfloat16 lx = __float2bfloat16(x - __bfloat162float(hx));
    __nv_bfloat16 ly = __float2bfloat16(y - __bfloat162float(hy));
    __nv_bfloat162 h2; h2.x = hx; h2.y = hy;
    __nv_bfloat162 l2; l2.x = lx; l2.y = ly;
    *(__nv_bfloat162*)(H + off) = h2;
    *(__nv_bfloat162*)(L + off) = l2;
}

// ---------------- bf16x3 mma.sync GEMM ---------------------------------------
// C[M,N] = (Ah+Al)[M,K] @ (Bh+Bl)^T + bias   (B stored [N][K] K-major)
// CTA 128x256, BK=32 bf16, 8 warps (2m x 4n), warp tile 64x64, 3-stage cp.async.
// 3 MMA terms: ah*bh + al*bh + ah*bl  (error ~2^-18).
#define GBM 128
#define GBN 256
#define GBK 32
#define SROW 80                         // bytes per smem row (32 bf16 + pad)
#define SA_H 0
#define SA_L (128 * SROW)               // 10240
#define SB_H (2 * 128 * SROW)           // 20480
#define SB_L (SB_H + 256 * SROW)        // 40960
#define STG_B (SB_L + 256 * SROW)       // 61440
#define NSTG 3
#define GEMM_SMEM (NSTG * STG_B)        // 184320

template<int OUTBF>
__global__ void __launch_bounds__(256, 1)
gemm_bf16x3(const __nv_bfloat16* __restrict__ Ah, const __nv_bfloat16* __restrict__ Al,
            const __nv_bfloat16* __restrict__ Bh, const __nv_bfloat16* __restrict__ Bl,
            const float* __restrict__ bias,
            float* __restrict__ Cf,
            __nv_bfloat16* __restrict__ Ch, __nv_bfloat16* __restrict__ Cl,
            int N, int K, int relu)
{
    extern __shared__ char sm[];
    const uint32_t sb = smem_u32(sm);
    const int tid = threadIdx.x, wid = tid >> 5, lane = tid & 31;
    const int wm = wid & 1, wn = wid >> 1;
    const int g = lane >> 2, tg = lane & 3;
    const int brow = blockIdx.y * GBM, bcol = blockIdx.x * GBN;
    const int ktiles = K / GBK;

    float acc[4][8][4];
    #pragma unroll
    for (int i = 0; i < 4; i++)
        #pragma unroll
        for (int j = 0; j < 8; j++)
            #pragma unroll
            for (int r = 0; r < 4; r++) acc[i][j][r] = 0.f;

    auto prefetch = [&](int kt) {
        uint32_t st = sb + (uint32_t)((kt % NSTG) * STG_B);
        const int koff = kt * GBK;
        #pragma unroll
        for (int i = 0; i < 2; i++) {
            int c = tid + i * 256, row = c >> 2, o = (c & 3) * 8;
            cp_async16(st + SA_H + row * SROW + o * 2,
                       Ah + (size_t)(brow + row) * K + koff + o);
            cp_async16(st + SA_L + row * SROW + o * 2,
                       Al + (size_t)(brow + row) * K + koff + o);
        }
        #pragma unroll
        for (int i = 0; i < 4; i++) {
            int c = tid + i * 256, row = c >> 2, o = (c & 3) * 8;
            cp_async16(st + SB_H + row * SROW + o * 2,
                       Bh + (size_t)(bcol + row) * K + koff + o);
            cp_async16(st + SB_L + row * SROW + o * 2,
                       Bl + (size_t)(bcol + row) * K + koff + o);
        }
        CP_COMMIT();
    };

    int issued = 0;
    for (; issued < NSTG - 1 && issued < ktiles; issued++) prefetch(issued);

    for (int kt = 0; kt < ktiles; kt++) {
        int pending = issued - kt - 1;
        if (pending >= 2)      CP_WAIT(2);
        else if (pending == 1) CP_WAIT(1);
        else                   CP_WAIT(0);
        __syncthreads();
        if (issued < ktiles) { prefetch(issued); issued++; }

        const char* stg = sm + (kt % NSTG) * STG_B;
        #pragma unroll
        for (int kk = 0; kk < GBK; kk += 16) {
            const int cby = (kk + tg * 2) * 2;   // byte offset of this thread's k pair
            uint32_t fah[4][4], fal[4][4];
            #pragma unroll
            for (int mt = 0; mt < 4; mt++) {
                const int r = wm * 64 + mt * 16 + g;
                const char* ph = stg + SA_H;
                const char* pl = stg + SA_L;
                fah[mt][0] = *(const uint32_t*)(ph + r * SROW + cby);
                fah[mt][1] = *(const uint32_t*)(ph + (r + 8) * SROW + cby);
                fah[mt][2] = *(const uint32_t*)(ph + r * SROW + cby + 16);
                fah[mt][3] = *(const uint32_t*)(ph + (r + 8) * SROW + cby + 16);
                fal[mt][0] = *(const uint32_t*)(pl + r * SROW + cby);
                fal[mt][1] = *(const uint32_t*)(pl + (r + 8) * SROW + cby);
                fal[mt][2] = *(const uint32_t*)(pl + r * SROW + cby + 16);
                fal[mt][3] = *(const uint32_t*)(pl + (r + 8) * SROW + cby + 16);
            }
            #pragma unroll
            for (int nt = 0; nt < 8; nt++) {
                const int n = wn * 64 + nt * 8 + g;
                uint32_t bh0 = *(const uint32_t*)(stg + SB_H + n * SROW + cby);
                uint32_t bh1 = *(const uint32_t*)(stg + SB_H + n * SROW + cby + 16);
                uint32_t bl0 = *(const uint32_t*)(stg + SB_L + n * SROW + cby);
                uint32_t bl1 = *(const uint32_t*)(stg + SB_L + n * SROW + cby + 16);
                #pragma unroll
                for (int mt = 0; mt < 4; mt++) mma_bf16(acc[mt][nt], fah[mt], bh0, bh1);
                #pragma unroll
                for (int mt = 0; mt < 4; mt++) mma_bf16(acc[mt][nt], fal[mt], bh0, bh1);
                #pragma unroll
                for (int mt = 0; mt < 4; mt++) mma_bf16(acc[mt][nt], fah[mt], bl0, bl1);
            }
        }
    }

    // ---- epilogue ----
    #pragma unroll
    for (int mt = 0; mt < 4; mt++) {
        const int gr = brow + wm * 64 + mt * 16 + g;
        #pragma unroll
        for (int nt = 0; nt < 8; nt++) {
            const int gc = bcol + wn * 64 + nt * 8 + tg * 2;
            float2 bb = *(const float2*)(bias + gc);
            float v0x = acc[mt][nt][0] + bb.x, v0y = acc[mt][nt][1] + bb.y;
            float v1x = acc[mt][nt][2] + bb.x, v1y = acc[mt][nt][3] + bb.y;
            if (relu) {
                v0x = fmaxf(v0x, 0.f); v0y = fmaxf(v0y, 0.f);
                v1x = fmaxf(v1x, 0.f); v1y = fmaxf(v1y, 0.f);
            }
            if (OUTBF == 0) {
                float2 a = {v0x, v0y}, b = {v1x, v1y};
                *(float2*)(Cf + (size_t)gr * N + gc)       = a;
                *(float2*)(Cf + (size_t)(gr + 8) * N + gc) = b;
            } else {
                store_split2(Ch, Cl, (size_t)gr * N + gc, v0x, v0y);
                store_split2(Ch, Cl, (size_t)(gr + 8) * N + gc, v1x, v1y);
            }
        }
    }
}

// ---------------- preprocessing ----------------------------------------------
__global__ void split_f32(const float* __restrict__ in,
                          __nv_bfloat16* __restrict__ H, __nv_bfloat16* __restrict__ L, int n2)
{
    int i = blockIdx.x * blockDim.x + threadIdx.x;
    if (i < n2) {
        float2 v = ((const float2*)in)[i];
        store_split2(H, L, (size_t)i * 2, v.x, v.y);
    }
}

// in[R][C] fp32 -> out[C][R] bf16 hi/lo
__global__ void transpose_split(const float* __restrict__ in,
                                __nv_bfloat16* __restrict__ OH, __nv_bfloat16* __restrict__ OL,
                                int R, int C)
{
    __shared__ float t[32][33];
    int c0 = blockIdx.x * 32, r0 = blockIdx.y * 32;
    for (int i = threadIdx.y; i < 32; i += 8)
        t[i][threadIdx.x] = in[(size_t)(r0 + i) * C + c0 + threadIdx.x];
    __syncthreads();
    for (int i = threadIdx.y; i < 32; i += 8) {
        float v = t[threadIdx.x][i];
        __nv_bfloat16 h = __float2bfloat16(v);
        __nv_bfloat16 l = __float2bfloat16(v - __bfloat162float(h));
        OH[(size_t)(c0 + i) * R + r0 + threadIdx.x] = h;
        OL[(size_t)(c0 + i) * R + r0 + threadIdx.x] = l;
    }
}

// ---------------- attention: flash-style fp32, writes bf16 hi/lo ctx ---------
#define QT 128
#define KT 64
#define CH 16

__global__ void __launch_bounds__(128)
attn_kernel(const float* __restrict__ Q, const float* __restrict__ K,
            const float* __restrict__ V, const int* __restrict__ lengths,
            __nv_bfloat16* __restrict__ CtxH, __nv_bfloat16* __restrict__ CtxL)
{
    __shared__ float Ksh[KT][HDIM];
    __shared__ float Vsh[KT][HDIM];

    const int b    = blockIdx.z;
    const int head = blockIdx.y;
    const int q0   = blockIdx.x * QT;
    const int tid  = threadIdx.x;
    const int len  = lengths[b];

    float q[HDIM];
    const float* qrow = Q + ((size_t)(b * SS) + q0 + tid) * DD + head * HDIM;
    #pragma unroll
    for (int d = 0; d < HDIM; d += 4) {
        float4 t = *(const float4*)(qrow + d);
        q[d] = t.x; q[d + 1] = t.y; q[d + 2] = t.z; q[d + 3] = t.w;
    }

    float acc[HDIM];
    #pragma unroll
    for (int d = 0; d < HDIM; d++) acc[d] = 0.f;
    float m = -1e30f, l = 0.f;
    const float scale = 0.125f;

    const int ntiles = (len + KT - 1) / KT;
    for (int t = 0; t < ntiles; t++) {
        const int kbase = t * KT;
        __syncthreads();
        for (int i = tid; i < KT * (HDIM / 4); i += 128) {
            int kr = i / (HDIM / 4);
            int dc = (i % (HDIM / 4)) * 4;
            size_t goff = ((size_t)(b * SS) + kbase + kr) * DD + head * HDIM + dc;
            *(float4*)&Ksh[kr][dc] = *(const float4*)(K + goff);
            *(float4*)&Vsh[kr][dc] = *(const float4*)(V + goff);
        }
        __syncthreads();

        const int kmax = min(KT, len - kbase);
        for (int base = 0; base < kmax; base += CH) {
            float s[CH];
            float tmax = -1e30f;
            #pragma unroll
            for (int k = 0; k < CH; k++) {
                const int kk = base + k;
                float dot = 0.f;
                #pragma unroll
                for (int d = 0; d < HDIM; d++) dot += q[d] * Ksh[kk][d];
                s[k] = (kk < kmax) ? dot * scale : -1e30f;
                tmax = fmaxf(tmax, s[k]);
            }
            if (tmax > m) {
                float alpha = __expf(m - tmax);
                m = tmax;
                l *= alpha;
                #pragma unroll
                for (int d = 0; d < HDIM; d++) acc[d] *= alpha;
            }
            float psum = 0.f;
            #pragma unroll
            for (int k = 0; k < CH; k++) {
                float p = __expf(s[k] - m);
                psum += p;
                #pragma unroll
                for (int d = 0; d < HDIM; d++) acc[d] += p * Vsh[base + k][d];
            }
            l += psum;
        }
    }

    const float inv = 1.f / l;
    const size_t obase = ((size_t)(b * SS) + q0 + tid) * DD + head * HDIM;
    #pragma unroll
    for (int d = 0; d < HDIM; d += 2)
        store_split2(CtxH, CtxL, obase + d, acc[d] * inv, acc[d + 1] * inv);
}

// ---------------- host side --------------------------------------------------
template<typename T>
static T* sym_addr(const void* sym) {
    void* p = nullptr;
    cudaGetSymbolAddress(&p, sym);
    return (T*)p;
}

extern "C" void kernel_launch(void* const* d_in, const int* in_sizes, int n_in,
                              void* d_out, int out_size)
{
    const float* x   = (const float*)d_in[0];
    const int*   len = (const int*)  d_in[1];
    const float* qW  = (const float*)d_in[2];
    const float* qb  = (const float*)d_in[3];
    const float* kW  = (const float*)d_in[4];
    const float* kb  = (const float*)d_in[5];
    const float* vW  = (const float*)d_in[6];
    const float* vb  = (const float*)d_in[7];
    const float* oW  = (const float*)d_in[8];
    const float* ob  = (const float*)d_in[9];
    const float* w1  = (const float*)d_in[10];
    const float* b1  = (const float*)d_in[11];
    const float* w2  = (const float*)d_in[12];
    const float* b2  = (const float*)d_in[13];
    float* out = (float*)d_out;

    typedef __nv_bfloat16 bf;
    static float* pq  = sym_addr<float>(g_q);
    static float* pk  = sym_addr<float>(g_k);
    static float* pv  = sym_addr<float>(g_v);
    static bf* pxh = sym_addr<bf>(g_xh);  static bf* pxl = sym_addr<bf>(g_xl);
    static bf* pch = sym_addr<bf>(g_ch);  static bf* pcl = sym_addr<bf>(g_cl);
    static bf* pth = sym_addr<bf>(g_th);  static bf* ptl = sym_addr<bf>(g_tl);
    static bf* pfh = sym_addr<bf>(g_fh);  static bf* pfl = sym_addr<bf>(g_fl);
    static bf* pwh = sym_addr<bf>(g_wh);  static bf* pwl = sym_addr<bf>(g_wl);

    static bool inited = false;
    if (!inited) {
        cudaFuncSetAttribute(gemm_bf16x3<0>, cudaFuncAttributeMaxDynamicSharedMemorySize, GEMM_SMEM);
        cudaFuncSetAttribute(gemm_bf16x3<1>, cudaFuncAttributeMaxDynamicSharedMemorySize, GEMM_SMEM);
        inited = true;
    }

    const uint32_t M1 = 1024u * 1024u;
    bf *wq_h = pwh,          *wq_l = pwl;
    bf *wk_h = pwh + 1 * M1, *wk_l = pwl + 1 * M1;
    bf *wv_h = pwh + 2 * M1, *wv_l = pwl + 2 * M1;
    bf *wo_h = pwh + 3 * M1, *wo_l = pwl + 3 * M1;
    bf *w1_h = pwh + 4 * M1, *w1_l = pwl + 4 * M1;
    bf *w2_h = pwh + 8 * M1, *w2_l = pwl + 8 * M1;

    // preprocess: split x; transpose+split all weights to [N][K] bf16 hi/lo
    split_f32<<<(MM * DD / 2 + 255) / 256, 256>>>(x, pxh, pxl, MM * DD / 2);
    dim3 tb(32, 8);
    transpose_split<<<dim3(32, 32), tb>>>(qW, wq_h, wq_l, DD, DD);
    transpose_split<<<dim3(32, 32), tb>>>(kW, wk_h, wk_l, DD, DD);
    transpose_split<<<dim3(32, 32), tb>>>(vW, wv_h, wv_l, DD, DD);
    transpose_split<<<dim3(32, 32), tb>>>(oW, wo_h, wo_l, DD, DD);
    transpose_split<<<dim3(FFD / 32, 32), tb>>>(w1, w1_h, w1_l, DD, FFD);  // -> [FF][D]
    transpose_split<<<dim3(32, FFD / 32), tb>>>(w2, w2_h, w2_l, FFD, DD);  // -> [D][FF]

    dim3 thr(256);
    dim3 gD(DD / GBN, MM / GBM);    // (4, 64)
    dim3 gF(FFD / GBN, MM / GBM);   // (16, 64)

    gemm_bf16x3<0><<<gD, thr, GEMM_SMEM>>>(pxh, pxl, wq_h, wq_l, qb, pq, nullptr, nullptr, DD, DD, 0);
    gemm_bf16x3<0><<<gD, thr, GEMM_SMEM>>>(pxh, pxl, wk_h, wk_l, kb, pk, nullptr, nullptr, DD, DD, 0);
    gemm_bf16x3<0><<<gD, thr, GEMM_SMEM>>>(pxh, pxl, wv_h, wv_l, vb, pv, nullptr, nullptr, DD, DD, 0);

    dim3 ga(SS / QT, HH, BB);
    attn_kernel<<<ga, 128>>>(pq, pk, pv, len, pch, pcl);

    gemm_bf16x3<1><<<gD, thr, GEMM_SMEM>>>(pch, pcl, wo_h, wo_l, ob, nullptr, pth, ptl, DD, DD, 0);
    gemm_bf16x3<1><<<gF, thr, GEMM_SMEM>>>(pth, ptl, w1_h, w1_l, b1, nullptr, pfh, pfl, FFD, DD, 1);
    gemm_bf16x3<0><<<gD, thr, GEMM_SMEM>>>(pfh, pfl, w2_h, w2_l, b2, out, nullptr, nullptr, DD, FFD, 0);
}

// round 6
// speedup vs baseline: 2.8203x; 1.9317x over previous
#include <cuda_runtime.h>
#include <cuda_bf16.h>
#include <math.h>
#include <stdint.h>

#define BB 4
#define SS 2048
#define DD 1024
#define HH 16
#define HDIM 64
#define FFD 4096
#define MM (BB * SS)
#define QKVN 3072

__device__ float g_qkv[(size_t)MM * QKVN];
__device__ float g_bias[QKVN];
__device__ __nv_bfloat16 g_xh[(size_t)MM * DD],  g_xl[(size_t)MM * DD];
__device__ __nv_bfloat16 g_ch[(size_t)MM * DD],  g_cl[(size_t)MM * DD];
__device__ __nv_bfloat16 g_th[(size_t)MM * DD],  g_tl[(size_t)MM * DD];
__device__ __nv_bfloat16 g_fh[(size_t)MM * FFD], g_fl[(size_t)MM * FFD];
__device__ __nv_bfloat16 g_wh[12u * 1024u * 1024u];
__device__ __nv_bfloat16 g_wl[12u * 1024u * 1024u];

__device__ __forceinline__ uint32_t smem_u32(const void* p) {
    uint32_t a;
    asm("{ .reg .u64 t; cvta.to.shared.u64 t, %1; cvt.u32.u64 %0, t; }" : "=r"(a) : "l"(p));
    return a;
}
__device__ __forceinline__ uint32_t tf32_rna(float x) {
    uint32_t r; asm("cvt.rna.tf32.f32 %0, %1;" : "=r"(r) : "f"(x)); return r;
}
__device__ __forceinline__ void cp_async16(uint32_t dst, const void* src) {
    asm volatile("cp.async.cg.shared.global [%0], [%1], 16;" :: "r"(dst), "l"(src));
}
#define CP_COMMIT() asm volatile("cp.async.commit_group;" ::: "memory")
#define CP_WAIT0()  asm volatile("cp.async.wait_group 0;" ::: "memory")

__device__ __forceinline__ void ldm_x4(uint32_t* r, uint32_t a) {
    asm volatile("ldmatrix.sync.aligned.m8n8.x4.shared.b16 {%0,%1,%2,%3}, [%4];"
                 : "=r"(r[0]), "=r"(r[1]), "=r"(r[2]), "=r"(r[3]) : "r"(a));
}
__device__ __forceinline__ void mma_bf16(float* c, const uint32_t* a, uint32_t b0, uint32_t b1) {
    asm volatile("mma.sync.aligned.m16n8k16.row.col.f32.bf16.bf16.f32 "
        "{%0,%1,%2,%3}, {%4,%5,%6,%7}, {%8,%9}, {%0,%1,%2,%3};"
        : "+f"(c[0]), "+f"(c[1]), "+f"(c[2]), "+f"(c[3])
        : "r"(a[0]), "r"(a[1]), "r"(a[2]), "r"(a[3]), "r"(b0), "r"(b1));
}
__device__ __forceinline__ void mma_tf32(float* c, const uint32_t* a, uint32_t b0, uint32_t b1) {
    asm volatile("mma.sync.aligned.m16n8k8.row.col.f32.tf32.tf32.f32 "
        "{%0,%1,%2,%3}, {%4,%5,%6,%7}, {%8,%9}, {%0,%1,%2,%3};"
        : "+f"(c[0]), "+f"(c[1]), "+f"(c[2]), "+f"(c[3])
        : "r"(a[0]), "r"(a[1]), "r"(a[2]), "r"(a[3]), "r"(b0), "r"(b1));
}
__device__ __forceinline__ void store_split2(__nv_bfloat16* __restrict__ H,
                                             __nv_bfloat16* __restrict__ L,
                                             size_t off, float x, float y) {
    __nv_bfloat16 hx = __float2bfloat16(x), hy = __float2bfloat16(y);
    __nv_bfloat16 lx = __float2bfloat16(x - __bfloat162float(hx));
    __nv_bfloat16 ly = __float2bfloat16(y - __bfloat162float(hy));
    __nv_bfloat162 h2; h2.x = hx; h2.y = hy;
    __nv_bfloat162 l2; l2.x = lx; l2.y = ly;
    *(__nv_bfloat162*)(H + off) = h2;
    *(__nv_bfloat162*)(L + off) = l2;
}

// ============ bf16x3 GEMM: ldmatrix + swizzle, BK=64, 2-stage ==============
#define GBM 128
#define GBN 256
#define GBK 64
#define AH_OFF 0
#define AL_OFF 16384
#define BH_OFF 32768
#define BL_OFF 65536
#define STG_B  98304
#define GEMM_SMEM (2 * STG_B)
#define FL_RELU 1
#define FL_TF32 2

template<int OUTBF>
__global__ void __launch_bounds__(256, 1)
gemm_bf16x3(const __nv_bfloat16* __restrict__ Ah, const __nv_bfloat16* __restrict__ Al,
            const __nv_bfloat16* __restrict__ Bh, const __nv_bfloat16* __restrict__ Bl,
            const float* __restrict__ bias, float* __restrict__ Cf,
            __nv_bfloat16* __restrict__ Ch, __nv_bfloat16* __restrict__ Cl,
            int N, int K, int flags)
{
    extern __shared__ char sm[];
    const uint32_t sb = smem_u32(sm);
    const int tid = threadIdx.x, wid = tid >> 5, lane = tid & 31;
    const int wm = wid & 1, wn = wid >> 1;
    const int g = lane >> 2, tg = lane & 3;
    const int brow = blockIdx.y * GBM, bcol = blockIdx.x * GBN;
    const int ktiles = K / GBK;
    const uint32_t sw7 = lane & 7;
    const uint32_t cselA = (lane >> 4) & 1, cselB = (lane >> 3) & 1;
    uint32_t baseA[4], baseB[4];
    #pragma unroll
    for (int mt = 0; mt < 4; mt++)
        baseA[mt] = (uint32_t)((wm * 64 + mt * 16 + (lane & 7) + ((lane >> 3) & 1) * 8) * 128);
    #pragma unroll
    for (int np = 0; np < 4; np++)
        baseB[np] = (uint32_t)((wn * 64 + np * 16 + (lane & 7) + ((lane >> 4) & 1) * 8) * 128);

    float acc[4][8][4];
    #pragma unroll
    for (int i = 0; i < 4; i++)
        #pragma unroll
        for (int j = 0; j < 8; j++) { acc[i][j][0]=0.f; acc[i][j][1]=0.f; acc[i][j][2]=0.f; acc[i][j][3]=0.f; }

    auto fill = [&](int kt) {
        const uint32_t stg = sb + (uint32_t)((kt & 1) * STG_B);
        const int koff = kt * GBK;
        #pragma unroll
        for (int i = 0; i < 4; i++) {
            int id = tid + i * 256, row = id >> 3, c = id & 7;
            uint32_t d = stg + row * 128 + (((uint32_t)c ^ (row & 7)) << 4);
            size_t go = (size_t)(brow + row) * K + koff + c * 8;
            cp_async16(d + AH_OFF, Ah + go);
            cp_async16(d + AL_OFF, Al + go);
        }
        #pragma unroll
        for (int i = 0; i < 8; i++) {
            int id = tid + i * 256, row = id >> 3, c = id & 7;
            uint32_t d = stg + row * 128 + (((uint32_t)c ^ (row & 7)) << 4);
            size_t go = (size_t)(bcol + row) * K + koff + c * 8;
            cp_async16(d + BH_OFF, Bh + go);
            cp_async16(d + BL_OFF, Bl + go);
        }
        CP_COMMIT();
    };

    fill(0);
    for (int kt = 0; kt < ktiles; kt++) {
        CP_WAIT0();
        __syncthreads();
        if (kt + 1 < ktiles) fill(kt + 1);
        const uint32_t stg = sb + (uint32_t)((kt & 1) * STG_B);
        #pragma unroll
        for (uint32_t kk8 = 0; kk8 < 8; kk8 += 2) {
            uint32_t fah[4][4], fal[4][4];
            #pragma unroll
            for (int mt = 0; mt < 4; mt++) {
                uint32_t ad = stg + AH_OFF + baseA[mt] + (((kk8 + cselA) ^ sw7) << 4);
                ldm_x4(fah[mt], ad);
                ldm_x4(fal[mt], ad + (AL_OFF - AH_OFF));
            }
            uint32_t bh[8][2], bl[8][2];
            #pragma unroll
            for (int np = 0; np < 4; np++) {
                uint32_t bd = stg + BH_OFF + baseB[np] + (((kk8 + cselB) ^ sw7) << 4);
                uint32_t r[4];
                ldm_x4(r, bd);
                bh[2*np][0]=r[0]; bh[2*np][1]=r[1]; bh[2*np+1][0]=r[2]; bh[2*np+1][1]=r[3];
                ldm_x4(r, bd + (BL_OFF - BH_OFF));
                bl[2*np][0]=r[0]; bl[2*np][1]=r[1]; bl[2*np+1][0]=r[2]; bl[2*np+1][1]=r[3];
            }
            #pragma unroll
            for (int nt = 0; nt < 8; nt++) {
                #pragma unroll
                for (int mt = 0; mt < 4; mt++) mma_bf16(acc[mt][nt], fah[mt], bh[nt][0], bh[nt][1]);
                #pragma unroll
                for (int mt = 0; mt < 4; mt++) mma_bf16(acc[mt][nt], fal[mt], bh[nt][0], bh[nt][1]);
                #pragma unroll
                for (int mt = 0; mt < 4; mt++) mma_bf16(acc[mt][nt], fah[mt], bl[nt][0], bl[nt][1]);
            }
        }
    }

    const int do_relu = flags & FL_RELU, do_t32 = flags & FL_TF32;
    #pragma unroll
    for (int mt = 0; mt < 4; mt++) {
        const int gr = brow + wm * 64 + mt * 16 + g;
        #pragma unroll
        for (int nt = 0; nt < 8; nt++) {
            const int gc = bcol + wn * 64 + nt * 8 + tg * 2;
            float2 bb = *(const float2*)(bias + gc);
            float v0x = acc[mt][nt][0] + bb.x, v0y = acc[mt][nt][1] + bb.y;
            float v1x = acc[mt][nt][2] + bb.x, v1y = acc[mt][nt][3] + bb.y;
            if (do_relu) {
                v0x = fmaxf(v0x, 0.f); v0y = fmaxf(v0y, 0.f);
                v1x = fmaxf(v1x, 0.f); v1y = fmaxf(v1y, 0.f);
            }
            if (OUTBF == 0) {
                if (do_t32) {
                    v0x = __uint_as_float(tf32_rna(v0x)); v0y = __uint_as_float(tf32_rna(v0y));
                    v1x = __uint_as_float(tf32_rna(v1x)); v1y = __uint_as_float(tf32_rna(v1y));
                }
                float2 a = {v0x, v0y}, b = {v1x, v1y};
                *(float2*)(Cf + (size_t)gr * N + gc)       = a;
                *(float2*)(Cf + (size_t)(gr + 8) * N + gc) = b;
            } else {
                store_split2(Ch, Cl, (size_t)gr * N + gc, v0x, v0y);
                store_split2(Ch, Cl, (size_t)(gr + 8) * N + gc, v1x, v1y);
            }
        }
    }
}

// ============ tensor-core attention (tf32 mma) ==============================
#define KVROWB  304
#define KMAT    (32 * KVROWB)
#define KVSTAGE (2 * KMAT)
#define PBASE   (2 * KVSTAGE)
#define PROWB   144
#define PWARP   (16 * PROWB)
#define ATTN_SMEM (PBASE + 8 * PWARP)   // 57344

__global__ void __launch_bounds__(256, 2)
attn_tc(const float* __restrict__ qkv, const int* __restrict__ lengths,
        __nv_bfloat16* __restrict__ CtxH, __nv_bfloat16* __restrict__ CtxL)
{
    extern __shared__ char sm[];
    const uint32_t sb = smem_u32(sm);
    const int tid = threadIdx.x, wid = tid >> 5, lane = tid & 31;
    const int g = lane >> 2, tg = lane & 3;
    const int b = blockIdx.z, h = blockIdx.y;
    const int q0 = blockIdx.x * 128;
    const int len = lengths[b];

    const float* Qb = qkv + (size_t)(b * SS + q0 + wid * 16) * QKVN + h * HDIM;
    uint32_t qf[8][4];
    #pragma unroll
    for (int kc = 0; kc < 8; kc++) {
        qf[kc][0] = __float_as_uint(Qb[(size_t)g * QKVN + kc * 8 + tg] * 0.125f);
        qf[kc][1] = __float_as_uint(Qb[(size_t)(g + 8) * QKVN + kc * 8 + tg] * 0.125f);
        qf[kc][2] = __float_as_uint(Qb[(size_t)g * QKVN + kc * 8 + tg + 4] * 0.125f);
        qf[kc][3] = __float_as_uint(Qb[(size_t)(g + 8) * QKVN + kc * 8 + tg + 4] * 0.125f);
    }

    float acc[8][4];
    #pragma unroll
    for (int i = 0; i < 8; i++) { acc[i][0]=0.f; acc[i][1]=0.f; acc[i][2]=0.f; acc[i][3]=0.f; }
    float m0 = -1e30f, m1 = -1e30f, l0 = 0.f, l1 = 0.f;

    const int ntiles = (len + 31) / 32;
    const uint32_t pbase = sb + PBASE + wid * PWARP;

    auto fill = [&](int t) {
        const uint32_t stg = sb + (uint32_t)((t & 1) * KVSTAGE);
        const int kbase = t * 32;
        #pragma unroll
        for (int i = 0; i < 4; i++) {
            int id = tid + i * 256;
            int mat = id >> 9, idm = id & 511, row = idm >> 4, c = idm & 15;
            uint32_t d = stg + mat * KMAT + row * KVROWB + c * 16;
            cp_async16(d, qkv + (size_t)(b * SS + kbase + row) * QKVN
                          + DD + mat * DD + h * HDIM + c * 4);
        }
        CP_COMMIT();
    };

    fill(0);
    for (int t = 0; t < ntiles; t++) {
        CP_WAIT0();
        __syncthreads();
        if (t + 1 < ntiles) fill(t + 1);
        const uint32_t stg = sb + (uint32_t)((t & 1) * KVSTAGE);
        const int rem = len - t * 32;

        float s[4][4];
        #pragma unroll
        for (int nt = 0; nt < 4; nt++) { s[nt][0]=0.f; s[nt][1]=0.f; s[nt][2]=0.f; s[nt][3]=0.f; }
        #pragma unroll
        for (int kc = 0; kc < 8; kc++) {
            #pragma unroll
            for (int nt = 0; nt < 4; nt++) {
                uint32_t ka = stg + (uint32_t)((nt * 8 + g) * KVROWB + (kc * 8 + tg) * 4);
                uint32_t b0, b1;
                asm volatile("ld.shared.b32 %0, [%1];" : "=r"(b0) : "r"(ka));
                asm volatile("ld.shared.b32 %0, [%1];" : "=r"(b1) : "r"(ka + 16));
                mma_tf32(s[nt], qf[kc], b0, b1);
            }
        }
        if (rem < 32) {
            #pragma unroll
            for (int nt = 0; nt < 4; nt++) {
                int c0 = nt * 8 + 2 * tg;
                if (c0 >= rem)     { s[nt][0] = -1e30f; s[nt][2] = -1e30f; }
                if (c0 + 1 >= rem) { s[nt][1] = -1e30f; s[nt][3] = -1e30f; }
            }
        }
        float mx0 = -1e30f, mx1 = -1e30f;
        #pragma unroll
        for (int nt = 0; nt < 4; nt++) {
            mx0 = fmaxf(mx0, fmaxf(s[nt][0], s[nt][1]));
            mx1 = fmaxf(mx1, fmaxf(s[nt][2], s[nt][3]));
        }
        mx0 = fmaxf(mx0, __shfl_xor_sync(0xffffffffu, mx0, 1));
        mx0 = fmaxf(mx0, __shfl_xor_sync(0xffffffffu, mx0, 2));
        mx1 = fmaxf(mx1, __shfl_xor_sync(0xffffffffu, mx1, 1));
        mx1 = fmaxf(mx1, __shfl_xor_sync(0xffffffffu, mx1, 2));
        float nm0 = fmaxf(m0, mx0), nm1 = fmaxf(m1, mx1);
        float a0 = __expf(m0 - nm0), a1 = __expf(m1 - nm1);
        m0 = nm0; m1 = nm1;
        l0 *= a0; l1 *= a1;
        #pragma unroll
        for (int nt = 0; nt < 8; nt++) {
            acc[nt][0] *= a0; acc[nt][1] *= a0;
            acc[nt][2] *= a1; acc[nt][3] *= a1;
        }
        float rs0 = 0.f, rs1 = 0.f;
        #pragma unroll
        for (int nt = 0; nt < 4; nt++) {
            float p0 = __expf(s[nt][0] - m0), p1 = __expf(s[nt][1] - m0);
            float p2 = __expf(s[nt][2] - m1), p3 = __expf(s[nt][3] - m1);
            rs0 += p0 + p1; rs1 += p2 + p3;
            uint32_t pa = pbase + (uint32_t)(g * PROWB + (nt * 8 + 2 * tg) * 4);
            asm volatile("st.shared.v2.b32 [%0], {%1,%2};" :: "r"(pa), "r"(tf32_rna(p0)), "r"(tf32_rna(p1)) : "memory");
            asm volatile("st.shared.v2.b32 [%0], {%1,%2};" :: "r"(pa + 8 * PROWB), "r"(tf32_rna(p2)), "r"(tf32_rna(p3)) : "memory");
        }
        rs0 += __shfl_xor_sync(0xffffffffu, rs0, 1);
        rs0 += __shfl_xor_sync(0xffffffffu, rs0, 2);
        rs1 += __shfl_xor_sync(0xffffffffu, rs1, 1);
        rs1 += __shfl_xor_sync(0xffffffffu, rs1, 2);
        l0 += rs0; l1 += rs1;
        __syncwarp();
        const uint32_t vbase = stg + KMAT;
        #pragma unroll
        for (int kc = 0; kc < 4; kc++) {
            uint32_t pf[4];
            uint32_t pa = pbase + (uint32_t)(g * PROWB + (kc * 8 + tg) * 4);
            asm volatile("ld.shared.b32 %0, [%1];" : "=r"(pf[0]) : "r"(pa));
            asm volatile("ld.shared.b32 %0, [%1];" : "=r"(pf[1]) : "r"(pa + 8 * PROWB));
            asm volatile("ld.shared.b32 %0, [%1];" : "=r"(pf[2]) : "r"(pa + 16));
            asm volatile("ld.shared.b32 %0, [%1];" : "=r"(pf[3]) : "r"(pa + 8 * PROWB + 16));
            #pragma unroll
            for (int nt = 0; nt < 8; nt++) {
                uint32_t va = vbase + (uint32_t)((kc * 8 + tg) * KVROWB + (nt * 8 + g) * 4);
                uint32_t b0, b1;
                asm volatile("ld.shared.b32 %0, [%1];" : "=r"(b0) : "r"(va));
                asm volatile("ld.shared.b32 %0, [%1];" : "=r"(b1) : "r"(va + 4 * KVROWB));
                mma_tf32(acc[nt], pf, b0, b1);
            }
        }
        __syncwarp();
    }

    const float i0 = 1.f / l0, i1 = 1.f / l1;
    const size_t r0 = (size_t)(b * SS + q0 + wid * 16 + g) * DD + h * HDIM;
    const size_t r1 = (size_t)(b * SS + q0 + wid * 16 + g + 8) * DD + h * HDIM;
    #pragma unroll
    for (int nt = 0; nt < 8; nt++) {
        int col = nt * 8 + 2 * tg;
        store_split2(CtxH, CtxL, r0 + col, acc[nt][0] * i0, acc[nt][1] * i0);
        store_split2(CtxH, CtxL, r1 + col, acc[nt][2] * i1, acc[nt][3] * i1);
    }
}

// ============ preprocessing ==================================================
__global__ void split_f32(const float* __restrict__ in,
                          __nv_bfloat16* __restrict__ H, __nv_bfloat16* __restrict__ L, int n2)
{
    int i = blockIdx.x * blockDim.x + threadIdx.x;
    if (i < n2) {
        float2 v = ((const float2*)in)[i];
        store_split2(H, L, (size_t)i * 2, v.x, v.y);
    }
}
__global__ void transpose_split(const float* __restrict__ in,
                                __nv_bfloat16* __restrict__ OH, __nv_bfloat16* __restrict__ OL,
                                int R, int C)
{
    __shared__ float t[32][33];
    int c0 = blockIdx.x * 32, r0 = blockIdx.y * 32;
    for (int i = threadIdx.y; i < 32; i += 8)
        t[i][threadIdx.x] = in[(size_t)(r0 + i) * C + c0 + threadIdx.x];
    __syncthreads();
    for (int i = threadIdx.y; i < 32; i += 8) {
        float v = t[threadIdx.x][i];
        __nv_bfloat16 hh = __float2bfloat16(v);
        __nv_bfloat16 ll = __float2bfloat16(v - __bfloat162float(hh));
        OH[(size_t)(c0 + i) * R + r0 + threadIdx.x] = hh;
        OL[(size_t)(c0 + i) * R + r0 + threadIdx.x] = ll;
    }
}
__global__ void concat_bias(const float* __restrict__ qb, const float* __restrict__ kb,
                            const float* __restrict__ vb, float* __restrict__ o)
{
    int i = blockIdx.x * blockDim.x + threadIdx.x;
    if (i < QKVN) o[i] = (i < DD) ? qb[i] : (i < 2 * DD) ? kb[i - DD] : vb[i - 2 * DD];
}

// ============ host ===========================================================
template<typename T>
static T* sym_addr(const void* sym) {
    void* p = nullptr; cudaGetSymbolAddress(&p, sym); return (T*)p;
}

extern "C" void kernel_launch(void* const* d_in, const int* in_sizes, int n_in,
                              void* d_out, int out_size)
{
    const float* x   = (const float*)d_in[0];
    const int*   len = (const int*)  d_in[1];
    const float* qW  = (const float*)d_in[2];
    const float* qb  = (const float*)d_in[3];
    const float* kW  = (const float*)d_in[4];
    const float* kb  = (const float*)d_in[5];
    const float* vW  = (const float*)d_in[6];
    const float* vb  = (const float*)d_in[7];
    const float* oW  = (const float*)d_in[8];
    const float* ob  = (const float*)d_in[9];
    const float* w1  = (const float*)d_in[10];
    const float* b1  = (const float*)d_in[11];
    const float* w2  = (const float*)d_in[12];
    const float* b2  = (const float*)d_in[13];
    float* out = (float*)d_out;

    typedef __nv_bfloat16 bf;
    static float* pqkv = sym_addr<float>(g_qkv);
    static float* pbia = sym_addr<float>(g_bias);
    static bf* pxh = sym_addr<bf>(g_xh);  static bf* pxl = sym_addr<bf>(g_xl);
    static bf* pch = sym_addr<bf>(g_ch);  static bf* pcl = sym_addr<bf>(g_cl);
    static bf* pth = sym_addr<bf>(g_th);  static bf* ptl = sym_addr<bf>(g_tl);
    static bf* pfh = sym_addr<bf>(g_fh);  static bf* pfl = sym_addr<bf>(g_fl);
    static bf* pwh = sym_addr<bf>(g_wh);  static bf* pwl = sym_addr<bf>(g_wl);

    static bool inited = false;
    if (!inited) {
        cudaFuncSetAttribute(gemm_bf16x3<0>, cudaFuncAttributeMaxDynamicSharedMemorySize, GEMM_SMEM);
        cudaFuncSetAttribute(gemm_bf16x3<1>, cudaFuncAttributeMaxDynamicSharedMemorySize, GEMM_SMEM);
        cudaFuncSetAttribute(attn_tc, cudaFuncAttributeMaxDynamicSharedMemorySize, ATTN_SMEM);
        inited = true;
    }

    const size_t M1 = 1024u * 1024u;
    bf *wqkv_h = pwh,          *wqkv_l = pwl;
    bf *wo_h   = pwh + 3 * M1, *wo_l   = pwl + 3 * M1;
    bf *w1_h   = pwh + 4 * M1, *w1_l   = pwl + 4 * M1;
    bf *w2_h   = pwh + 8 * M1, *w2_l   = pwl + 8 * M1;

    split_f32<<<(MM * DD / 2 + 255) / 256, 256>>>(x, pxh, pxl, MM * DD / 2);
    dim3 tb(32, 8);
    transpose_split<<<dim3(32, 32), tb>>>(qW, wqkv_h,          wqkv_l,          DD, DD);
    transpose_split<<<dim3(32, 32), tb>>>(kW, wqkv_h + 1 * M1, wqkv_l + 1 * M1, DD, DD);
    transpose_split<<<dim3(32, 32), tb>>>(vW, wqkv_h + 2 * M1, wqkv_l + 2 * M1, DD, DD);
    transpose_split<<<dim3(32, 32), tb>>>(oW, wo_h, wo_l, DD, DD);
    transpose_split<<<dim3(FFD / 32, 32), tb>>>(w1, w1_h, w1_l, DD, FFD);
    transpose_split<<<dim3(32, FFD / 32), tb>>>(w2, w2_h, w2_l, FFD, DD);
    concat_bias<<<(QKVN + 255) / 256, 256>>>(qb, kb, vb, pbia);

    dim3 thr(256);
    gemm_bf16x3<0><<<dim3(QKVN / GBN, MM / GBM), thr, GEMM_SMEM>>>(
        pxh, pxl, wqkv_h, wqkv_l, pbia, pqkv, nullptr, nullptr, QKVN, DD, FL_TF32);

    attn_tc<<<dim3(SS / 128, HH, BB), 256, ATTN_SMEM>>>(pqkv, len, pch, pcl);

    gemm_bf16x3<1><<<dim3(DD / GBN, MM / GBM), thr, GEMM_SMEM>>>(
        pch, pcl, wo_h, wo_l, ob, nullptr, pth, ptl, DD, DD, 0);
    gemm_bf16x3<1><<<dim3(FFD / GBN, MM / GBM), thr, GEMM_SMEM>>>(
        pth, ptl, w1_h, w1_l, b1, nullptr, pfh, pfl, FFD, DD, FL_RELU);
    gemm_bf16x3<0><<<dim3(DD / GBN, MM / GBM), thr, GEMM_SMEM>>>(
        pfh, pfl, w2_h, w2_l, b2, out, nullptr, nullptr, DD, FFD, 0);
}